// round 10
// baseline (speedup 1.0000x reference)
#include <cuda_runtime.h>
#include <cstdint>

// Problem constants
#define B_NUM  4
#define T_SEQ  2048
#define C_DIM  2048
#define H_NUM  16
#define D_HEAD 128

// ---------------------------------------------------------------------------
// Scratch (no cudaMalloc allowed): qkv [B,T,3C] and attention output [B,T,C]
// ---------------------------------------------------------------------------
__device__ float g_qkv[(size_t)B_NUM * T_SEQ * 3 * C_DIM];
__device__ float g_att[(size_t)B_NUM * T_SEQ * C_DIM];

// ---------------------------------------------------------------------------
// tf32 / math helpers
// ---------------------------------------------------------------------------
__device__ __forceinline__ uint32_t f2tf32(float x) {
    uint32_t r;
    asm("cvt.rna.tf32.f32 %0, %1;" : "=r"(r) : "f"(x));
    return r;
}
__device__ __forceinline__ uint32_t bits2tf32(uint32_t b) {
    uint32_t r;
    asm("cvt.rna.tf32.f32 %0, %1;" : "=r"(r) : "f"(__uint_as_float(b)));
    return r;
}
__device__ __forceinline__ float fexp2(float x) {   // raw EX2, no pre-multiply
    float y;
    asm("ex2.approx.ftz.f32 %0, %1;" : "=f"(y) : "f"(x));
    return y;
}

// D += A(16x8) * B(8x8), tf32 in, f32 accumulate
__device__ __forceinline__ void mma_tf32(float d[4], const uint32_t a[4], const uint32_t b[2]) {
    asm("mma.sync.aligned.m16n8k8.row.col.f32.tf32.tf32.f32 "
        "{%0,%1,%2,%3}, {%4,%5,%6,%7}, {%8,%9}, {%0,%1,%2,%3};\n"
        : "+f"(d[0]), "+f"(d[1]), "+f"(d[2]), "+f"(d[3])
        : "r"(a[0]), "r"(a[1]), "r"(a[2]), "r"(a[3]), "r"(b[0]), "r"(b[1]));
}

__device__ __forceinline__ void cpasync16(uint32_t smaddr, const void* gptr) {
    asm volatile("cp.async.cg.shared.global [%0], [%1], 16;\n" :: "r"(smaddr), "l"(gptr));
}
__device__ __forceinline__ void cpasync_commit() {
    asm volatile("cp.async.commit_group;\n" ::: "memory");
}
template <int N>
__device__ __forceinline__ void cpasync_wait() {
    asm volatile("cp.async.wait_group %0;\n" :: "n"(N) : "memory");
}

// ---------------------------------------------------------------------------
// NT GEMM, 3-stage cp.async ring: C[M,N] = A[M,K] * B[N,K]^T
// BM=128, BN=128, BK=32, 256 threads, 8 warps (2 x 4), warp tile 64x32.
// One barrier per k-tile: wait<1> -> barrier -> compute(i) -> issue(i+2).
// Issue targets slot (i+2)%3 = (i-1)%3; safe because every thread issuing has
// passed barrier(i), which proves all warps finished reading stage i-1.
// Raw fp32 staged in smem; cvt.rna -> tf32 at fragment read.
// __launch_bounds__(256,2): cap 128 regs; 2 CTAs/SM at 108KB smem each.
// ---------------------------------------------------------------------------
#define G_BM 128
#define G_BN 128
#define G_BK 32
#define G_STR 36   // smem row stride in words (4*row + k mod 32 -> conflict free)
#define G_TILE (G_BM * G_STR)           // words per matrix per stage
#define G_STAGES 3
#define G_SMEM (G_STAGES * 2 * G_TILE * 4)   // 108 KB

__global__ __launch_bounds__(256, 2) void gemm_nt_tf32_db(
    const float* __restrict__ A, const float* __restrict__ B,
    float* __restrict__ C, int M, int N, int K)
{
    extern __shared__ uint32_t sm[];
    // stage s: A at sm + s*2*G_TILE, B at sm + s*2*G_TILE + G_TILE

    const int bm = blockIdx.y * G_BM;
    const int bn = blockIdx.x * G_BN;
    const int tid  = threadIdx.x;
    const int warp = tid >> 5;
    const int lane = tid & 31;
    const int g    = lane >> 2;   // group id (0..7)
    const int tig  = lane & 3;    // thread in group
    const int wm = (warp >> 2) * 64;  // warp row offset
    const int wn = (warp & 3) * 32;   // warp col offset

    const int lr = tid >> 3;        // 0..31
    const int lc = (tid & 7) * 4;   // 0..28

    const float* Abase = A + (size_t)bm * K;
    const float* Bbase = B + (size_t)bn * K;

    float acc[4][4][4];
#pragma unroll
    for (int i = 0; i < 4; i++)
#pragma unroll
        for (int j = 0; j < 4; j++) {
            acc[i][j][0] = 0.f; acc[i][j][1] = 0.f;
            acc[i][j][2] = 0.f; acc[i][j][3] = 0.f;
        }

    const int ntiles = K / G_BK;

    // ---- prologue: issue stages 0 and 1 (one commit group each) ----
#pragma unroll
    for (int s = 0; s < 2; s++) {
        uint32_t sa = (uint32_t)__cvta_generic_to_shared(sm + s * 2 * G_TILE);
        uint32_t sb = sa + G_TILE * 4;
        const int k0 = s * G_BK;
#pragma unroll
        for (int rr = 0; rr < 4; rr++) {
            int row = lr + rr * 32;
            cpasync16(sa + (row * G_STR + lc) * 4, Abase + (size_t)row * K + k0 + lc);
            cpasync16(sb + (row * G_STR + lc) * 4, Bbase + (size_t)row * K + k0 + lc);
        }
        cpasync_commit();
    }

    int cur = 0;        // ring slot holding stage i
    int nxt = 2;        // ring slot to receive stage i+2
    for (int i = 0; i < ntiles; i++) {
        if (i + 1 < ntiles) cpasync_wait<1>();   // stage i resident (i+1 may fly)
        else                cpasync_wait<0>();   // last stage: drain all
        __syncthreads();

        const uint32_t* As = sm + cur * 2 * G_TILE;
        const uint32_t* Bs = As + G_TILE;

#pragma unroll
        for (int ks = 0; ks < 4; ks++) {
            const int c = ks * 8 + tig;
            uint32_t af[4][4];
            uint32_t bf[4][2];
#pragma unroll
            for (int mf = 0; mf < 4; mf++) {
                int r = wm + mf * 16 + g;
                af[mf][0] = bits2tf32(As[r * G_STR + c]);
                af[mf][1] = bits2tf32(As[(r + 8) * G_STR + c]);
                af[mf][2] = bits2tf32(As[r * G_STR + c + 4]);
                af[mf][3] = bits2tf32(As[(r + 8) * G_STR + c + 4]);
            }
#pragma unroll
            for (int nf = 0; nf < 4; nf++) {
                int n = wn + nf * 8 + g;
                bf[nf][0] = bits2tf32(Bs[n * G_STR + c]);
                bf[nf][1] = bits2tf32(Bs[n * G_STR + c + 4]);
            }
#pragma unroll
            for (int mf = 0; mf < 4; mf++)
#pragma unroll
                for (int nf = 0; nf < 4; nf++)
                    mma_tf32(acc[mf][nf], af[mf], bf[nf]);
        }

        // ---- issue stage i+2 into slot nxt (overwrites stage i-1's slot) ----
        if (i + 2 < ntiles) {
            const int k0 = (i + 2) * G_BK;
            uint32_t sa = (uint32_t)__cvta_generic_to_shared(sm + nxt * 2 * G_TILE);
            uint32_t sb = sa + G_TILE * 4;
#pragma unroll
            for (int rr = 0; rr < 4; rr++) {
                int row = lr + rr * 32;
                cpasync16(sa + (row * G_STR + lc) * 4, Abase + (size_t)row * K + k0 + lc);
                cpasync16(sb + (row * G_STR + lc) * 4, Bbase + (size_t)row * K + k0 + lc);
            }
            cpasync_commit();
        }

        cur = (cur == G_STAGES - 1) ? 0 : cur + 1;
        nxt = (nxt == G_STAGES - 1) ? 0 : nxt + 1;
    }

#pragma unroll
    for (int mf = 0; mf < 4; mf++) {
        int r = bm + wm + mf * 16 + g;
#pragma unroll
        for (int nf = 0; nf < 4; nf++) {
            int cc = bn + wn + nf * 8 + 2 * tig;
            *reinterpret_cast<float2*>(&C[(size_t)r * N + cc]) =
                make_float2(acc[mf][nf][0], acc[mf][nf][1]);
            *reinterpret_cast<float2*>(&C[(size_t)(r + 8) * N + cc]) =
                make_float2(acc[mf][nf][2], acc[mf][nf][3]);
        }
    }
}

// ---------------------------------------------------------------------------
// Flash attention (causal), tf32 MMA, online softmax (base-2 domain),
// cp.async pipelined.
// Block: 256 threads (8 warps), 128 queries per block, 64-key tiles, d=128.
// Each warp owns 16 query rows; Q fragments persistent in registers.
// Smem: K double buffer (stride 132, row-wise reads) + V buffer (stride 136,
// transposed reads -> conflict-free) + P (tf32, 64-bit packed stores).
// Pipeline: issue V(j); wait K(j); S-MMA; issue K(j+1); wait V(j); softmax+PV.
// Fully-masked warp-tiles skip compute, keep barriers.
// LPT scheduling: qt reversed vs blockIdx.x so longest blocks launch first.
// ---------------------------------------------------------------------------
#define Q_TILE 128
#define KV_STR 132   // K/Q buffers: bank = 4g+tig on row-wise fragment reads
#define V_STR  136   // V buffer: bank = 8*tig+g on transposed PV reads
#define P_STR  68    // 64 + 4 pad
#define KV_TILE (64 * KV_STR)
#define V_TILE  (64 * V_STR)
#define ATT_SMEM ((2 * KV_TILE + V_TILE + Q_TILE * P_STR) * 4)

// async-stage one 64 x 128 fp32 tile (global row stride 3*C_DIM), 256 threads
__device__ __forceinline__ void cp_tile64(uint32_t saddr, const float* __restrict__ src,
                                          int tid, int sstr)
{
#pragma unroll
    for (int i = 0; i < 8; i++) {
        int idx = tid + i * 256;          // 0..2047
        int r = idx >> 5;                 // 0..63
        int c4 = (idx & 31) << 2;
        cpasync16(saddr + (r * sstr + c4) * 4, src + (size_t)r * (3 * C_DIM) + c4);
    }
}

__global__ __launch_bounds__(256, 1) void attn_kernel(const float* __restrict__ qkv,
                                                      float* __restrict__ out)
{
    extern __shared__ uint32_t sm[];
    uint32_t* sK0 = sm;                      // K stage 0 (Q rows 0-63 in prologue)
    uint32_t* sK1 = sm + KV_TILE;            // K stage 1 (Q rows 64-127 in prologue)
    uint32_t* sV  = sm + 2 * KV_TILE;        // V (stride V_STR)
    uint32_t* sP  = sm + 2 * KV_TILE + V_TILE; // P tile [128][P_STR]

    const uint32_t sK0a = (uint32_t)__cvta_generic_to_shared(sK0);
    const uint32_t sK1a = (uint32_t)__cvta_generic_to_shared(sK1);
    const uint32_t sVa  = (uint32_t)__cvta_generic_to_shared(sV);

    // LPT: longest blocks (largest qt) get the smallest bid -> scheduled first
    const int qt = gridDim.x - 1 - blockIdx.x;   // query tile (128 rows)
    const int b  = blockIdx.y >> 4;
    const int h  = blockIdx.y & 15;
    const int tid  = threadIdx.x;
    const int warp = tid >> 5;
    const int lane = tid & 31;
    const int g   = lane >> 2;
    const int tig = lane & 3;
    const int wq  = warp * 16;           // warp's query-row offset within tile (0..112)
    // base-2 softmax domain: scale' = (1/sqrt(128)) * log2(e)
    const float scale = 0.12751744f;

    const float* qbase = qkv + (size_t)b * T_SEQ * 3 * C_DIM + h * D_HEAD;
    const float* kbase = qbase + C_DIM;
    const float* vbase = qbase + 2 * C_DIM;

    // ---- prologue: stage Q halves into sK0/sK1, lift tf32 fragments ----
    cp_tile64(sK0a, qbase + (size_t)(qt * Q_TILE) * (3 * C_DIM), tid, KV_STR);
    cp_tile64(sK1a, qbase + (size_t)(qt * Q_TILE + 64) * (3 * C_DIM), tid, KV_STR);
    cpasync_commit();
    cpasync_wait<0>();
    __syncthreads();

    const uint32_t* qsrc = (warp < 4) ? sK0 : sK1;
    const int qrow = wq & 63;            // row within the chosen half
    uint32_t qf[16][4];
#pragma unroll
    for (int ks = 0; ks < 16; ks++) {
        int c = ks * 8 + tig;
        qf[ks][0] = bits2tf32(qsrc[(qrow + g) * KV_STR + c]);
        qf[ks][1] = bits2tf32(qsrc[(qrow + g + 8) * KV_STR + c]);
        qf[ks][2] = bits2tf32(qsrc[(qrow + g) * KV_STR + c + 4]);
        qf[ks][3] = bits2tf32(qsrc[(qrow + g + 8) * KV_STR + c + 4]);
    }
    __syncthreads();   // all Q fragment reads done before K(0) overwrites sK0

    // kick K(0)                                      (flight: K0)
    cp_tile64(sK0a, kbase + 0, tid, KV_STR);
    cpasync_commit();

    float of[16][4];
#pragma unroll
    for (int i = 0; i < 16; i++) { of[i][0] = 0.f; of[i][1] = 0.f; of[i][2] = 0.f; of[i][3] = 0.f; }
    float m0 = -1e30f, m1 = -1e30f, l0 = 0.f, l1 = 0.f;

    const int gr0 = qt * Q_TILE + wq + g;   // global query row 0
    const int jmax = 2 * qt + 1;            // last 64-key tile index

    for (int j = 0; j <= jmax; j++) {
        const uint32_t* sKc = (j & 1) ? sK1 : sK0;
        const uint32_t  sKna = (j & 1) ? sK0a : sK1a;

        // this warp's 16 rows all precede every key in tile j -> dead work
        const bool live = (j * 64 <= qt * Q_TILE + wq + 15);

        __syncthreads();   // all reads of sV (V(j-1)) complete

        // issue V(j)                                (flight: K(j), V(j))
        cp_tile64(sVa, vbase + (size_t)(j * 64) * (3 * C_DIM), tid, V_STR);
        cpasync_commit();

        cpasync_wait<1>(); // K(j) resident
        __syncthreads();

        // S = Q K^T  (16 x 64 per warp)
        float sacc[8][4];
#pragma unroll
        for (int nf = 0; nf < 8; nf++) { sacc[nf][0]=0.f; sacc[nf][1]=0.f; sacc[nf][2]=0.f; sacc[nf][3]=0.f; }
        if (live) {
#pragma unroll
            for (int ks = 0; ks < 16; ks++) {
                int c = ks * 8 + tig;
#pragma unroll
                for (int nf = 0; nf < 8; nf++) {
                    uint32_t bfr[2];
                    bfr[0] = bits2tf32(sKc[(nf * 8 + g) * KV_STR + c]);
                    bfr[1] = bits2tf32(sKc[(nf * 8 + g) * KV_STR + c + 4]);
                    mma_tf32(sacc[nf], qf[ks], bfr);
                }
            }
        }

        // issue K(j+1) into the other K buffer      (flight: V(j) [, K(j+1)])
        if (j < jmax) {
            cp_tile64(sKna, kbase + (size_t)((j + 1) * 64) * (3 * C_DIM), tid, KV_STR);
            cpasync_commit();
            cpasync_wait<1>(); // V(j) resident, K(j+1) may fly
        } else {
            cpasync_wait<0>();
        }
        __syncthreads();

        if (live) {
            // scale (base-2 logits) + causal mask (diagonal tiles only)
#pragma unroll
            for (int nf = 0; nf < 8; nf++) {
                sacc[nf][0] *= scale; sacc[nf][1] *= scale;
                sacc[nf][2] *= scale; sacc[nf][3] *= scale;
            }
            if ((j + 1) * 64 - 1 > qt * Q_TILE + wq) {
                int r1 = gr0 + 8;
#pragma unroll
                for (int nf = 0; nf < 8; nf++) {
                    int gcb = j * 64 + nf * 8 + 2 * tig;
                    if (gcb     > gr0) sacc[nf][0] = -1e30f;
                    if (gcb + 1 > gr0) sacc[nf][1] = -1e30f;
                    if (gcb     > r1)  sacc[nf][2] = -1e30f;
                    if (gcb + 1 > r1)  sacc[nf][3] = -1e30f;
                }
            }

            // online softmax in base-2 domain (rows gr0, gr0+8)
            float mx0 = -1e30f, mx1 = -1e30f;
#pragma unroll
            for (int nf = 0; nf < 8; nf++) {
                mx0 = fmaxf(mx0, fmaxf(sacc[nf][0], sacc[nf][1]));
                mx1 = fmaxf(mx1, fmaxf(sacc[nf][2], sacc[nf][3]));
            }
            mx0 = fmaxf(mx0, __shfl_xor_sync(0xffffffffu, mx0, 1));
            mx0 = fmaxf(mx0, __shfl_xor_sync(0xffffffffu, mx0, 2));
            mx1 = fmaxf(mx1, __shfl_xor_sync(0xffffffffu, mx1, 1));
            mx1 = fmaxf(mx1, __shfl_xor_sync(0xffffffffu, mx1, 2));
            float mn0 = fmaxf(m0, mx0), mn1 = fmaxf(m1, mx1);
            float a0 = fexp2(m0 - mn0), a1 = fexp2(m1 - mn1);
            m0 = mn0; m1 = mn1;

            float rs0 = 0.f, rs1 = 0.f;
#pragma unroll
            for (int nf = 0; nf < 8; nf++) {
                float p0 = fexp2(sacc[nf][0] - mn0);
                float p1 = fexp2(sacc[nf][1] - mn0);
                float p2 = fexp2(sacc[nf][2] - mn1);
                float p3 = fexp2(sacc[nf][3] - mn1);
                rs0 += p0 + p1; rs1 += p2 + p3;
                int cb = nf * 8 + 2 * tig;
                *reinterpret_cast<uint2*>(&sP[(wq + g) * P_STR + cb]) =
                    make_uint2(f2tf32(p0), f2tf32(p1));
                *reinterpret_cast<uint2*>(&sP[(wq + g + 8) * P_STR + cb]) =
                    make_uint2(f2tf32(p2), f2tf32(p3));
            }
            rs0 += __shfl_xor_sync(0xffffffffu, rs0, 1);
            rs0 += __shfl_xor_sync(0xffffffffu, rs0, 2);
            rs1 += __shfl_xor_sync(0xffffffffu, rs1, 1);
            rs1 += __shfl_xor_sync(0xffffffffu, rs1, 2);
            l0 = l0 * a0 + rs0;
            l1 = l1 * a1 + rs1;
#pragma unroll
            for (int nf = 0; nf < 16; nf++) {
                of[nf][0] *= a0; of[nf][1] *= a0;
                of[nf][2] *= a1; of[nf][3] *= a1;
            }
            __syncwarp();  // sP visible to whole warp (warp-private rows)

            // O += P V  (P: 16x64 tf32 in sP, V: 64x128 fp32 in sV)
#pragma unroll
            for (int ks = 0; ks < 8; ks++) {
                int c = ks * 8 + tig;
                uint32_t pf[4];
                pf[0] = sP[(wq + g) * P_STR + c];
                pf[1] = sP[(wq + g + 8) * P_STR + c];
                pf[2] = sP[(wq + g) * P_STR + c + 4];
                pf[3] = sP[(wq + g + 8) * P_STR + c + 4];
#pragma unroll
                for (int nf = 0; nf < 16; nf++) {
                    uint32_t bfr[2];
                    bfr[0] = bits2tf32(sV[(ks * 8 + tig) * V_STR + nf * 8 + g]);
                    bfr[1] = bits2tf32(sV[(ks * 8 + tig + 4) * V_STR + nf * 8 + g]);
                    mma_tf32(of[nf], pf, bfr);
                }
            }
        }
    }

    // epilogue: normalize and write [B,T,C] with head interleave
    float i0 = 1.f / l0, i1 = 1.f / l1;
    int r0 = gr0;
    int r1 = gr0 + 8;
    float* o0 = out + ((size_t)b * T_SEQ + r0) * C_DIM + h * D_HEAD;
    float* o1 = out + ((size_t)b * T_SEQ + r1) * C_DIM + h * D_HEAD;
#pragma unroll
    for (int nf = 0; nf < 16; nf++) {
        int cb = nf * 8 + 2 * tig;
        *reinterpret_cast<float2*>(&o0[cb]) = make_float2(of[nf][0] * i0, of[nf][1] * i0);
        *reinterpret_cast<float2*>(&o1[cb]) = make_float2(of[nf][2] * i1, of[nf][3] * i1);
    }
}

// ---------------------------------------------------------------------------
// kernel_launch
// ---------------------------------------------------------------------------
extern "C" void kernel_launch(void* const* d_in, const int* in_sizes, int n_in,
                              void* d_out, int out_size)
{
    (void)in_sizes; (void)n_in; (void)out_size;
    const float* x  = (const float*)d_in[0];   // [B,T,C]
    const float* Wa = (const float*)d_in[1];   // [3C, C]
    const float* Wp = (const float*)d_in[2];   // [C, C]
    float* out = (float*)d_out;                // [B,T,C]

    float *qkv, *att;
    cudaGetSymbolAddress((void**)&qkv, g_qkv);
    cudaGetSymbolAddress((void**)&att, g_att);

    cudaFuncSetAttribute(gemm_nt_tf32_db, cudaFuncAttributeMaxDynamicSharedMemorySize, G_SMEM);
    cudaFuncSetAttribute(attn_kernel, cudaFuncAttributeMaxDynamicSharedMemorySize, ATT_SMEM);

    const int M = B_NUM * T_SEQ;   // 8192

    // 1) qkv = x @ W_attn^T   [8192, 6144]
    dim3 g1(3 * C_DIM / G_BN, M / G_BM);
    gemm_nt_tf32_db<<<g1, 256, G_SMEM>>>(x, Wa, qkv, M, 3 * C_DIM, C_DIM);

    // 2) causal flash attention -> att [B,T,C]
    dim3 g2(T_SEQ / Q_TILE, B_NUM * H_NUM);
    attn_kernel<<<g2, 256, ATT_SMEM>>>(qkv, att);

    // 3) out = att @ W_proj^T  [8192, 2048]
    dim3 g3(C_DIM / G_BN, M / G_BM);
    gemm_nt_tf32_db<<<g3, 256, G_SMEM>>>(att, Wp, out, M, C_DIM, C_DIM);
}

// round 13
// speedup vs baseline: 1.1141x; 1.1141x over previous
#include <cuda_runtime.h>
#include <cstdint>

// Problem constants
#define B_NUM  4
#define T_SEQ  2048
#define C_DIM  2048
#define H_NUM  16
#define D_HEAD 128

// ---------------------------------------------------------------------------
// Scratch (no cudaMalloc allowed). All values below are tf32-pre-rounded:
// inputs by the round pre-pass, qkv by the QKV GEMM epilogue, att by the
// attention epilogue. Rounding once at write is value-identical to rounding
// at every read — every hot loop feeds raw bits straight into MMA.
// ---------------------------------------------------------------------------
__device__ float g_qkv[(size_t)B_NUM * T_SEQ * 3 * C_DIM];
__device__ float g_att[(size_t)B_NUM * T_SEQ * C_DIM];
__device__ float g_x  [(size_t)B_NUM * T_SEQ * C_DIM];        // x, tf32
__device__ float g_wa [(size_t)3 * C_DIM * C_DIM];            // W_attn, tf32
__device__ float g_wp [(size_t)C_DIM * C_DIM];                // W_proj, tf32

// ---------------------------------------------------------------------------
// tf32 / math helpers
// ---------------------------------------------------------------------------
__device__ __forceinline__ uint32_t f2tf32(float x) {
    uint32_t r;
    asm("cvt.rna.tf32.f32 %0, %1;" : "=r"(r) : "f"(x));
    return r;
}
__device__ __forceinline__ float fexp2(float x) {   // raw EX2, no pre-multiply
    float y;
    asm("ex2.approx.ftz.f32 %0, %1;" : "=f"(y) : "f"(x));
    return y;
}

// D += A(16x8) * B(8x8), tf32 in, f32 accumulate
__device__ __forceinline__ void mma_tf32(float d[4], const uint32_t a[4], const uint32_t b[2]) {
    asm("mma.sync.aligned.m16n8k8.row.col.f32.tf32.tf32.f32 "
        "{%0,%1,%2,%3}, {%4,%5,%6,%7}, {%8,%9}, {%0,%1,%2,%3};\n"
        : "+f"(d[0]), "+f"(d[1]), "+f"(d[2]), "+f"(d[3])
        : "r"(a[0]), "r"(a[1]), "r"(a[2]), "r"(a[3]), "r"(b[0]), "r"(b[1]));
}

__device__ __forceinline__ void cpasync16(uint32_t smaddr, const void* gptr) {
    asm volatile("cp.async.cg.shared.global [%0], [%1], 16;\n" :: "r"(smaddr), "l"(gptr));
}
__device__ __forceinline__ void cpasync_commit() {
    asm volatile("cp.async.commit_group;\n" ::: "memory");
}
template <int N>
__device__ __forceinline__ void cpasync_wait() {
    asm volatile("cp.async.wait_group %0;\n" :: "n"(N) : "memory");
}

// ---------------------------------------------------------------------------
// Elementwise tf32 round pre-pass (float4 grid-stride)
// ---------------------------------------------------------------------------
__global__ void round_tf32_kernel(const float* __restrict__ in,
                                  float* __restrict__ outp, int n4)
{
    for (int i = blockIdx.x * blockDim.x + threadIdx.x; i < n4;
         i += gridDim.x * blockDim.x) {
        float4 v = reinterpret_cast<const float4*>(in)[i];
        v.x = __uint_as_float(f2tf32(v.x));
        v.y = __uint_as_float(f2tf32(v.y));
        v.z = __uint_as_float(f2tf32(v.z));
        v.w = __uint_as_float(f2tf32(v.w));
        reinterpret_cast<float4*>(outp)[i] = v;
    }
}

// ---------------------------------------------------------------------------
// NT GEMM, 3-stage cp.async ring: C[M,N] = A[M,K] * B[N,K]^T
// (verified R10 skeleton: regs=127, 2 CTAs/SM)
// Inputs are tf32-pre-rounded -> NO cvt in the hot loop.
// RTF: epilogue rounds outputs to tf32 (for the qkv intermediate).
// ---------------------------------------------------------------------------
#define G_BM 128
#define G_BN 128
#define G_BK 32
#define G_STR 36   // smem row stride in words (4*row + k mod 32 -> conflict free)
#define G_TILE (G_BM * G_STR)           // words per matrix per stage
#define G_STAGES 3
#define G_SMEM (G_STAGES * 2 * G_TILE * 4)   // 108 KB

template <bool RTF>
__global__ __launch_bounds__(256, 2) void gemm_nt_tf32_db(
    const float* __restrict__ A, const float* __restrict__ B,
    float* __restrict__ C, int M, int N, int K)
{
    extern __shared__ uint32_t sm[];

    const int bm = blockIdx.y * G_BM;
    const int bn = blockIdx.x * G_BN;
    const int tid  = threadIdx.x;
    const int warp = tid >> 5;
    const int lane = tid & 31;
    const int g    = lane >> 2;   // group id (0..7)
    const int tig  = lane & 3;    // thread in group
    const int wm = (warp >> 2) * 64;  // warp row offset
    const int wn = (warp & 3) * 32;   // warp col offset

    const int lr = tid >> 3;        // 0..31
    const int lc = (tid & 7) * 4;   // 0..28

    const float* Abase = A + (size_t)bm * K;
    const float* Bbase = B + (size_t)bn * K;

    float acc[4][4][4];
#pragma unroll
    for (int i = 0; i < 4; i++)
#pragma unroll
        for (int j = 0; j < 4; j++) {
            acc[i][j][0] = 0.f; acc[i][j][1] = 0.f;
            acc[i][j][2] = 0.f; acc[i][j][3] = 0.f;
        }

    const int ntiles = K / G_BK;

    // ---- prologue: issue stages 0 and 1 ----
#pragma unroll
    for (int s = 0; s < 2; s++) {
        uint32_t sa = (uint32_t)__cvta_generic_to_shared(sm + s * 2 * G_TILE);
        uint32_t sb = sa + G_TILE * 4;
        const int k0 = s * G_BK;
#pragma unroll
        for (int rr = 0; rr < 4; rr++) {
            int row = lr + rr * 32;
            cpasync16(sa + (row * G_STR + lc) * 4, Abase + (size_t)row * K + k0 + lc);
            cpasync16(sb + (row * G_STR + lc) * 4, Bbase + (size_t)row * K + k0 + lc);
        }
        cpasync_commit();
    }

    int cur = 0;
    int nxt = 2;
    for (int i = 0; i < ntiles; i++) {
        if (i + 1 < ntiles) cpasync_wait<1>();
        else                cpasync_wait<0>();
        __syncthreads();

        const uint32_t* As = sm + cur * 2 * G_TILE;
        const uint32_t* Bs = As + G_TILE;

#pragma unroll
        for (int ks = 0; ks < 4; ks++) {
            const int c = ks * 8 + tig;
            uint32_t af[4][4];
            uint32_t bf[4][2];
#pragma unroll
            for (int mf = 0; mf < 4; mf++) {
                int r = wm + mf * 16 + g;
                af[mf][0] = As[r * G_STR + c];
                af[mf][1] = As[(r + 8) * G_STR + c];
                af[mf][2] = As[r * G_STR + c + 4];
                af[mf][3] = As[(r + 8) * G_STR + c + 4];
            }
#pragma unroll
            for (int nf = 0; nf < 4; nf++) {
                int n = wn + nf * 8 + g;
                bf[nf][0] = Bs[n * G_STR + c];
                bf[nf][1] = Bs[n * G_STR + c + 4];
            }
#pragma unroll
            for (int mf = 0; mf < 4; mf++)
#pragma unroll
                for (int nf = 0; nf < 4; nf++)
                    mma_tf32(acc[mf][nf], af[mf], bf[nf]);
        }

        if (i + 2 < ntiles) {
            const int k0 = (i + 2) * G_BK;
            uint32_t sa = (uint32_t)__cvta_generic_to_shared(sm + nxt * 2 * G_TILE);
            uint32_t sb = sa + G_TILE * 4;
#pragma unroll
            for (int rr = 0; rr < 4; rr++) {
                int row = lr + rr * 32;
                cpasync16(sa + (row * G_STR + lc) * 4, Abase + (size_t)row * K + k0 + lc);
                cpasync16(sb + (row * G_STR + lc) * 4, Bbase + (size_t)row * K + k0 + lc);
            }
            cpasync_commit();
        }

        cur = (cur == G_STAGES - 1) ? 0 : cur + 1;
        nxt = (nxt == G_STAGES - 1) ? 0 : nxt + 1;
    }

#pragma unroll
    for (int mf = 0; mf < 4; mf++) {
        int r = bm + wm + mf * 16 + g;
#pragma unroll
        for (int nf = 0; nf < 4; nf++) {
            int cc = bn + wn + nf * 8 + 2 * tig;
            float v0 = acc[mf][nf][0], v1 = acc[mf][nf][1];
            float v2 = acc[mf][nf][2], v3 = acc[mf][nf][3];
            if (RTF) {   // pre-round to tf32 (value-identical to rounding at read)
                v0 = __uint_as_float(f2tf32(v0));
                v1 = __uint_as_float(f2tf32(v1));
                v2 = __uint_as_float(f2tf32(v2));
                v3 = __uint_as_float(f2tf32(v3));
            }
            *reinterpret_cast<float2*>(&C[(size_t)r * N + cc])       = make_float2(v0, v1);
            *reinterpret_cast<float2*>(&C[(size_t)(r + 8) * N + cc]) = make_float2(v2, v3);
        }
    }
}

// ---------------------------------------------------------------------------
// Flash attention (causal), tf32 MMA, base-2 online softmax.
// 256 threads (8 warps), 128 queries/block, 64-key tiles, d=128.
// Single barrier + single wait per iteration:
//   K triple-buffered (distance 2), V double-buffered (distance 1).
// qkv is tf32-pre-rounded -> NO cvt on Q/K/V fragment reads.
// Epilogue rounds att output to tf32 (consumed by the projection GEMM).
// Smem: 3*KV + 2*V + P = 201 KB (1 CTA/SM).
// ---------------------------------------------------------------------------
#define Q_TILE 128
#define KV_STR 132   // K/Q: bank = 4g+tig on row-wise fragment reads
#define V_STR  136   // V: bank = 8*tig+g on transposed PV reads
#define P_STR  68    // 64 + 4 pad
#define KV_TILE (64 * KV_STR)
#define V_TILE  (64 * V_STR)
#define ATT_SMEM ((3 * KV_TILE + 2 * V_TILE + Q_TILE * P_STR) * 4)

// async-stage one 64 x 128 fp32 tile (global row stride 3*C_DIM), 256 threads
__device__ __forceinline__ void cp_tile64(uint32_t saddr, const float* __restrict__ src,
                                          int tid, int sstr)
{
#pragma unroll
    for (int i = 0; i < 8; i++) {
        int idx = tid + i * 256;          // 0..2047
        int r = idx >> 5;                 // 0..63
        int c4 = (idx & 31) << 2;
        cpasync16(saddr + (r * sstr + c4) * 4, src + (size_t)r * (3 * C_DIM) + c4);
    }
}

__global__ __launch_bounds__(256, 1) void attn_kernel(const float* __restrict__ qkv,
                                                      float* __restrict__ out)
{
    extern __shared__ uint32_t sm[];
    uint32_t* sV0 = sm + 3 * KV_TILE;
    uint32_t* sV1 = sm + 3 * KV_TILE + V_TILE;
    uint32_t* sP  = sm + 3 * KV_TILE + 2 * V_TILE;   // [128][P_STR]
    uint32_t* sK2 = sm + 2 * KV_TILE;                // Q half-0 staging

    const uint32_t smb  = (uint32_t)__cvta_generic_to_shared(sm);
    const uint32_t sV0a = smb + (3 * KV_TILE) * 4;
    const uint32_t sV1a = sV0a + V_TILE * 4;
    const uint32_t sPa  = sV1a + V_TILE * 4;
    const uint32_t sK2a = smb + (2 * KV_TILE) * 4;

    // LPT: longest blocks (largest qt) get the smallest bid -> scheduled first
    const int qt = gridDim.x - 1 - blockIdx.x;   // query tile (128 rows)
    const int b  = blockIdx.y >> 4;
    const int h  = blockIdx.y & 15;
    const int tid  = threadIdx.x;
    const int warp = tid >> 5;
    const int lane = tid & 31;
    const int g   = lane >> 2;
    const int tig = lane & 3;
    const int wq  = warp * 16;           // warp's query-row offset within tile
    // base-2 softmax domain: scale' = (1/sqrt(128)) * log2(e)
    const float scale = 0.12751744f;

    const float* qbase = qkv + (size_t)b * T_SEQ * 3 * C_DIM + h * D_HEAD;
    const float* kbase = qbase + C_DIM;
    const float* vbase = qbase + 2 * C_DIM;

    // ---- prologue: stage Q halves into sK2 / sP, then kick G0..G2 ----
    cp_tile64(sK2a, qbase + (size_t)(qt * Q_TILE) * (3 * C_DIM), tid, KV_STR);
    cp_tile64(sPa,  qbase + (size_t)(qt * Q_TILE + 64) * (3 * C_DIM), tid, KV_STR);
    cpasync_commit();
    cpasync_wait<0>();
    __syncthreads();

    // commit Gk0 {K(0)}, Gv0 {V(0)}, Gk1 {K(1)} — slots untouched by Q staging
    cp_tile64(smb + 0 * KV_TILE * 4, kbase + 0, tid, KV_STR);
    cpasync_commit();
    cp_tile64(sV0a, vbase + 0, tid, V_STR);
    cpasync_commit();
    cp_tile64(smb + 1 * KV_TILE * 4, kbase + (size_t)64 * (3 * C_DIM), tid, KV_STR);
    cpasync_commit();

    // lift Q fragments (already tf32 bits; overlaps with in-flight loads)
    const uint32_t* qsrc = (warp < 4) ? sK2 : sP;
    const int qrow = (wq & 63);
    uint32_t qf[16][4];
#pragma unroll
    for (int ks = 0; ks < 16; ks++) {
        int c = ks * 8 + tig;
        qf[ks][0] = qsrc[(qrow + g) * KV_STR + c];
        qf[ks][1] = qsrc[(qrow + g + 8) * KV_STR + c];
        qf[ks][2] = qsrc[(qrow + g) * KV_STR + c + 4];
        qf[ks][3] = qsrc[(qrow + g + 8) * KV_STR + c + 4];
    }

    float of[16][4];
#pragma unroll
    for (int i = 0; i < 16; i++) { of[i][0] = 0.f; of[i][1] = 0.f; of[i][2] = 0.f; of[i][3] = 0.f; }
    float m0 = -1e30f, m1 = -1e30f, l0 = 0.f, l1 = 0.f;

    const int gr0 = qt * Q_TILE + wq + g;   // global query row 0
    const int jmax = 2 * qt + 1;            // last 64-key tile index

    for (int j = 0; j <= jmax; j++) {
        const uint32_t* sKc = sm + (j % 3) * KV_TILE;
        const uint32_t* sVc = (j & 1) ? sV1 : sV0;

        // this warp's 16 rows all precede every key in tile j -> dead work
        const bool live = (j * 64 <= qt * Q_TILE + wq + 15);

        if (j < jmax) cpasync_wait<1>();   // K(j), V(j) resident (Gk(j+1) may fly)
        else          cpasync_wait<0>();
        __syncthreads();                   // publish loads + close iter j-1 reads

        // prefetch: V(j+1) into slot (j+1)%2 [held V(j-1)], K(j+2) into (j+2)%3
        if (j + 1 <= jmax) {
            cp_tile64((j & 1) ? sV0a : sV1a,
                      vbase + (size_t)((j + 1) * 64) * (3 * C_DIM), tid, V_STR);
            cpasync_commit();
        }
        if (j + 2 <= jmax) {
            cp_tile64(smb + ((j + 2) % 3) * KV_TILE * 4,
                      kbase + (size_t)((j + 2) * 64) * (3 * C_DIM), tid, KV_STR);
            cpasync_commit();
        }

        // S = Q K^T  (16 x 64 per warp)  — K bits are tf32 already
        float sacc[8][4];
#pragma unroll
        for (int nf = 0; nf < 8; nf++) { sacc[nf][0]=0.f; sacc[nf][1]=0.f; sacc[nf][2]=0.f; sacc[nf][3]=0.f; }
        if (live) {
#pragma unroll
            for (int ks = 0; ks < 16; ks++) {
                int c = ks * 8 + tig;
#pragma unroll
                for (int nf = 0; nf < 8; nf++) {
                    uint32_t bfr[2];
                    bfr[0] = sKc[(nf * 8 + g) * KV_STR + c];
                    bfr[1] = sKc[(nf * 8 + g) * KV_STR + c + 4];
                    mma_tf32(sacc[nf], qf[ks], bfr);
                }
            }

            // scale (base-2 logits) + causal mask (diagonal tiles only)
#pragma unroll
            for (int nf = 0; nf < 8; nf++) {
                sacc[nf][0] *= scale; sacc[nf][1] *= scale;
                sacc[nf][2] *= scale; sacc[nf][3] *= scale;
            }
            if ((j + 1) * 64 - 1 > qt * Q_TILE + wq) {
                int r1 = gr0 + 8;
#pragma unroll
                for (int nf = 0; nf < 8; nf++) {
                    int gcb = j * 64 + nf * 8 + 2 * tig;
                    if (gcb     > gr0) sacc[nf][0] = -1e30f;
                    if (gcb + 1 > gr0) sacc[nf][1] = -1e30f;
                    if (gcb     > r1)  sacc[nf][2] = -1e30f;
                    if (gcb + 1 > r1)  sacc[nf][3] = -1e30f;
                }
            }

            // online softmax in base-2 domain (rows gr0, gr0+8)
            float mx0 = -1e30f, mx1 = -1e30f;
#pragma unroll
            for (int nf = 0; nf < 8; nf++) {
                mx0 = fmaxf(mx0, fmaxf(sacc[nf][0], sacc[nf][1]));
                mx1 = fmaxf(mx1, fmaxf(sacc[nf][2], sacc[nf][3]));
            }
            mx0 = fmaxf(mx0, __shfl_xor_sync(0xffffffffu, mx0, 1));
            mx0 = fmaxf(mx0, __shfl_xor_sync(0xffffffffu, mx0, 2));
            mx1 = fmaxf(mx1, __shfl_xor_sync(0xffffffffu, mx1, 1));
            mx1 = fmaxf(mx1, __shfl_xor_sync(0xffffffffu, mx1, 2));
            float mn0 = fmaxf(m0, mx0), mn1 = fmaxf(m1, mx1);
            float a0 = fexp2(m0 - mn0), a1 = fexp2(m1 - mn1);
            m0 = mn0; m1 = mn1;

            float rs0 = 0.f, rs1 = 0.f;
#pragma unroll
            for (int nf = 0; nf < 8; nf++) {
                float p0 = fexp2(sacc[nf][0] - mn0);
                float p1 = fexp2(sacc[nf][1] - mn0);
                float p2 = fexp2(sacc[nf][2] - mn1);
                float p3 = fexp2(sacc[nf][3] - mn1);
                rs0 += p0 + p1; rs1 += p2 + p3;
                int cb = nf * 8 + 2 * tig;
                *reinterpret_cast<uint2*>(&sP[(wq + g) * P_STR + cb]) =
                    make_uint2(f2tf32(p0), f2tf32(p1));
                *reinterpret_cast<uint2*>(&sP[(wq + g + 8) * P_STR + cb]) =
                    make_uint2(f2tf32(p2), f2tf32(p3));
            }
            rs0 += __shfl_xor_sync(0xffffffffu, rs0, 1);
            rs0 += __shfl_xor_sync(0xffffffffu, rs0, 2);
            rs1 += __shfl_xor_sync(0xffffffffu, rs1, 1);
            rs1 += __shfl_xor_sync(0xffffffffu, rs1, 2);
            l0 = l0 * a0 + rs0;
            l1 = l1 * a1 + rs1;
#pragma unroll
            for (int nf = 0; nf < 16; nf++) {
                of[nf][0] *= a0; of[nf][1] *= a0;
                of[nf][2] *= a1; of[nf][3] *= a1;
            }
            __syncwarp();  // sP visible to whole warp (warp-private rows)

            // O += P V  (P tf32 in sP, V tf32 bits in sVc)
#pragma unroll
            for (int ks = 0; ks < 8; ks++) {
                int c = ks * 8 + tig;
                uint32_t pf[4];
                pf[0] = sP[(wq + g) * P_STR + c];
                pf[1] = sP[(wq + g + 8) * P_STR + c];
                pf[2] = sP[(wq + g) * P_STR + c + 4];
                pf[3] = sP[(wq + g + 8) * P_STR + c + 4];
#pragma unroll
                for (int nf = 0; nf < 16; nf++) {
                    uint32_t bfr[2];
                    bfr[0] = sVc[(ks * 8 + tig) * V_STR + nf * 8 + g];
                    bfr[1] = sVc[(ks * 8 + tig + 4) * V_STR + nf * 8 + g];
                    mma_tf32(of[nf], pf, bfr);
                }
            }
        }
    }

    // epilogue: normalize, round to tf32 (proj GEMM reads raw), write [B,T,C]
    float i0 = 1.f / l0, i1 = 1.f / l1;
    int r0 = gr0;
    int r1 = gr0 + 8;
    float* o0 = out + ((size_t)b * T_SEQ + r0) * C_DIM + h * D_HEAD;
    float* o1 = out + ((size_t)b * T_SEQ + r1) * C_DIM + h * D_HEAD;
#pragma unroll
    for (int nf = 0; nf < 16; nf++) {
        int cb = nf * 8 + 2 * tig;
        *reinterpret_cast<float2*>(&o0[cb]) =
            make_float2(__uint_as_float(f2tf32(of[nf][0] * i0)),
                        __uint_as_float(f2tf32(of[nf][1] * i0)));
        *reinterpret_cast<float2*>(&o1[cb]) =
            make_float2(__uint_as_float(f2tf32(of[nf][2] * i1)),
                        __uint_as_float(f2tf32(of[nf][3] * i1)));
    }
}

// ---------------------------------------------------------------------------
// kernel_launch
// ---------------------------------------------------------------------------
extern "C" void kernel_launch(void* const* d_in, const int* in_sizes, int n_in,
                              void* d_out, int out_size)
{
    (void)in_sizes; (void)n_in; (void)out_size;
    const float* x  = (const float*)d_in[0];   // [B,T,C]
    const float* Wa = (const float*)d_in[1];   // [3C, C]
    const float* Wp = (const float*)d_in[2];   // [C, C]
    float* out = (float*)d_out;                // [B,T,C]

    float *qkv, *att, *xr, *war, *wpr;
    cudaGetSymbolAddress((void**)&qkv, g_qkv);
    cudaGetSymbolAddress((void**)&att, g_att);
    cudaGetSymbolAddress((void**)&xr,  g_x);
    cudaGetSymbolAddress((void**)&war, g_wa);
    cudaGetSymbolAddress((void**)&wpr, g_wp);

    cudaFuncSetAttribute(gemm_nt_tf32_db<true>,  cudaFuncAttributeMaxDynamicSharedMemorySize, G_SMEM);
    cudaFuncSetAttribute(gemm_nt_tf32_db<false>, cudaFuncAttributeMaxDynamicSharedMemorySize, G_SMEM);
    cudaFuncSetAttribute(attn_kernel, cudaFuncAttributeMaxDynamicSharedMemorySize, ATT_SMEM);

    const int M = B_NUM * T_SEQ;   // 8192

    // 0) tf32-round inputs once (hot loops then run cvt-free)
    round_tf32_kernel<<<2048, 256>>>(x,  xr,  (B_NUM * T_SEQ * C_DIM) / 4);
    round_tf32_kernel<<<2048, 256>>>(Wa, war, (3 * C_DIM * C_DIM) / 4);
    round_tf32_kernel<<<1024, 256>>>(Wp, wpr, (C_DIM * C_DIM) / 4);

    // 1) qkv = x @ W_attn^T   [8192, 6144], outputs tf32-pre-rounded
    dim3 g1(3 * C_DIM / G_BN, M / G_BM);
    gemm_nt_tf32_db<true><<<g1, 256, G_SMEM>>>(xr, war, qkv, M, 3 * C_DIM, C_DIM);

    // 2) causal flash attention -> att (tf32-rounded) [B,T,C]
    dim3 g2(T_SEQ / Q_TILE, B_NUM * H_NUM);
    attn_kernel<<<g2, 256, ATT_SMEM>>>(qkv, att);

    // 3) out = att @ W_proj^T  [8192, 2048], full fp32 outputs
    dim3 g3(C_DIM / G_BN, M / G_BM);
    gemm_nt_tf32_db<false><<<g3, 256, G_SMEM>>>(att, wpr, out, M, C_DIM, C_DIM);
}